// round 14
// baseline (speedup 1.0000x reference)
#include <cuda_runtime.h>
#include <cuda_bf16.h>
#include <cuda_fp16.h>
#include <cstdint>
#include <math.h>

#define B_   2
#define S_   2048
#define D_   4096
#define H_   32
#define HK_  8
#define HD_  128
#define M_   (B_ * S_)          // 4096 total tokens
#define KVD_ (HK_ * HD_)        // 1024
#define DP_  (D_ / 2)           // 2048 u32 pairs per row
#define SP_  (S_ / 2)           // 1024 seq pairs

// ---------------- scratch (device globals; no allocation allowed) ----------------
__device__ float    g_v[(size_t)M_ * KVD_];
// fp16 packed pair planes
__device__ unsigned g_x16[(size_t)M_ * DP_];
__device__ unsigned g_wq16[(size_t)D_ * DP_];
__device__ unsigned g_wk16[(size_t)KVD_ * DP_];
__device__ unsigned g_wv16[(size_t)KVD_ * DP_];
__device__ unsigned g_wo16[(size_t)D_ * DP_];
__device__ unsigned g_af16[(size_t)M_ * DP_];   // attention out (fp16 pairs)
__device__ unsigned g_q16[(size_t)M_ * DP_];                  // roped+scaled(log2e) Q (fp16)
__device__ unsigned g_k16[(size_t)B_ * HK_ * S_ * 64];        // roped K [b,hk,s,64]
__device__ unsigned g_vt16[(size_t)B_ * HK_ * HD_ * SP_];     // V^T [b,hk,d,s-pairs]

// ---------------- helpers ----------------
__device__ __forceinline__ unsigned packh2(float x, float y) {
    __half2 h = __floats2half2_rn(x, y);
    return *reinterpret_cast<unsigned*>(&h);
}

__device__ __forceinline__ void mma_fp16(float* c, const unsigned* a, unsigned b0, unsigned b1) {
    asm volatile(
        "mma.sync.aligned.m16n8k16.row.col.f32.f16.f16.f32 "
        "{%0,%1,%2,%3}, {%4,%5,%6,%7}, {%8,%9}, {%0,%1,%2,%3};\n"
        : "+f"(c[0]), "+f"(c[1]), "+f"(c[2]), "+f"(c[3])
        : "r"(a[0]), "r"(a[1]), "r"(a[2]), "r"(a[3]), "r"(b0), "r"(b1));
}

__device__ __forceinline__ void cpa16(unsigned saddr, const void* g) {
    asm volatile("cp.async.cg.shared.global [%0], [%1], 16;" :: "r"(saddr), "l"(g));
}

__device__ __forceinline__ uint32_t s2u(const void* p) {
    uint32_t a;
    asm("{ .reg .u64 t; cvta.to.shared.u64 t, %1; cvt.u32.u64 %0, t; }" : "=r"(a) : "l"(p));
    return a;
}

__device__ __forceinline__ void ldsm4(unsigned* r, uint32_t a) {
    asm volatile("ldmatrix.sync.aligned.m8n8.x4.shared.b16 {%0,%1,%2,%3}, [%4];"
                 : "=r"(r[0]), "=r"(r[1]), "=r"(r[2]), "=r"(r[3]) : "r"(a));
}

__device__ __forceinline__ void ldsm2(unsigned* r, uint32_t a) {
    asm volatile("ldmatrix.sync.aligned.m8n8.x2.shared.b16 {%0,%1}, [%2];"
                 : "=r"(r[0]), "=r"(r[1]) : "r"(a));
}

// ---------------- pack pass: fp32 -> fp16 pair plane ----------------
__global__ void pack16_kernel(const float* __restrict__ X,
                              unsigned* __restrict__ O, int npairs)
{
    int i = blockIdx.x * blockDim.x + threadIdx.x;
    if (i >= npairs) return;
    float2 v = ((const float2*)X)[i];
    O[i] = packh2(v.x, v.y);
}

// ---------------- transpose + pack V -> fp16 plane [b,hk,d,s-pairs] ----------------
__global__ void __launch_bounds__(256) transpose_pack_v(const float* __restrict__ V,
                                                        unsigned* __restrict__ O)
{
    __shared__ float sm[64 * 132];
    const int tid = threadIdx.x;
    const int s0  = blockIdx.x * 64;
    const int hk  = blockIdx.y;
    const int b   = blockIdx.z;

#pragma unroll
    for (int i = 0; i < 32; i++) {
        int idx = tid + i * 256;
        int r = idx >> 7, c = idx & 127;
        sm[r * 132 + c] = V[(size_t)(b * S_ + s0 + r) * KVD_ + hk * HD_ + c];
    }
    __syncthreads();

    const int d  = tid >> 1;
    const int pb = (tid & 1) * 16;
    unsigned* o = O + ((size_t)(b * HK_ + hk) * HD_ + d) * SP_ + (s0 >> 1) + pb;
#pragma unroll
    for (int i = 0; i < 16; i++) {
        int p = pb + i;
        o[i] = packh2(sm[(2 * p) * 132 + d], sm[(2 * p + 1) * 132 + d]);
    }
}

// =====================================================================
// fp16 single-stream GEMM (ldmatrix fragments) — unchanged from R13.
// =====================================================================
#define GSTR 36
#define APLU (256 * GSTR)
#define BPLU (128 * GSTR)
#define GSTGU (APLU + BPLU)
#define G_SMEM (3 * GSTGU * 4)        // 165888 B

template <int MODE>
__global__ void __launch_bounds__(512, 1)
gemm16(const unsigned* __restrict__ Ap, const unsigned* __restrict__ Bp,
       float* __restrict__ C, unsigned* __restrict__ O16,
       const float* __restrict__ cs, const float* __restrict__ sn,
       int N, int K)
{
    extern __shared__ unsigned gs[];

    const int tid  = threadIdx.x;
    const int lane = tid & 31;
    const int warp = tid >> 5;
    const int m0 = blockIdx.y << 8;
    const int n0 = blockIdx.x << 7;
    const int wm = (warp >> 2) * 64;
    const int wn = (warp & 3) * 32;
    const int grp = lane >> 2;
    const int qid = lane & 3;
    const int KP = K >> 1;

    const int lra = tid >> 1;
    const int lca = (tid & 1) * 16;
    const int lrb = tid >> 2;
    const int lcb = (tid & 3) * 8;
    const unsigned* ag = Ap + (size_t)(m0 + lra) * KP + lca;
    const unsigned* bg = Bp + (size_t)(n0 + lrb) * KP + lcb;

    const unsigned sbase = s2u(gs);
    const unsigned sra = (lra * GSTR + lca) * 4;
    const unsigned srb = (lrb * GSTR + lcb) * 4;

    const unsigned aoff = (unsigned)((wm + (lane & 15)) * GSTR * 4 + (lane >> 4) * 16);
    const unsigned boff = (unsigned)((wn + (lane >> 4) * 8 + (lane & 7)) * GSTR * 4
                                     + ((lane >> 3) & 1) * 16);

    float acc[4][4][4];
#pragma unroll
    for (int i = 0; i < 4; i++)
#pragma unroll
        for (int j = 0; j < 4; j++)
#pragma unroll
            for (int c = 0; c < 4; c++) acc[i][j][c] = 0.0f;

    const int nch = K / 64;

    auto issue = [&](int c, int stg) {
        unsigned sb = sbase + (unsigned)(stg * GSTGU * 4);
        const int go = c * 32;
        cpa16(sb + sra,                ag + go);
        cpa16(sb + sra + 16,           ag + go + 4);
        cpa16(sb + sra + 32,           ag + go + 8);
        cpa16(sb + sra + 48,           ag + go + 12);
        cpa16(sb + APLU * 4 + srb,       bg + go);
        cpa16(sb + APLU * 4 + srb + 16,  bg + go + 4);
        asm volatile("cp.async.commit_group;");
    };

    issue(0, 0);
    if (nch > 1) issue(1, 1);

    int stg = 0;
    for (int c = 0; c < nch; c++) {
        if (c + 2 < nch) issue(c + 2, (stg + 2) % 3);
        const int rem = nch - 1 - c;
        if (rem >= 2)      { asm volatile("cp.async.wait_group 2;"); }
        else if (rem == 1) { asm volatile("cp.async.wait_group 1;"); }
        else               { asm volatile("cp.async.wait_group 0;"); }
        __syncthreads();

        const unsigned sA = sbase + (unsigned)(stg * GSTGU * 4);
        const unsigned sB = sA + APLU * 4;

#pragma unroll
        for (int kk = 0; kk < 4; kk++) {
            unsigned af[4][4];
#pragma unroll
            for (int mi = 0; mi < 4; mi++)
                ldsm4(af[mi], sA + aoff + mi * (16 * GSTR * 4) + kk * 32);
#pragma unroll
            for (int njp = 0; njp < 2; njp++) {
                unsigned bf[4];
                ldsm4(bf, sB + boff + njp * (16 * GSTR * 4) + kk * 32);
#pragma unroll
                for (int mi = 0; mi < 4; mi++) {
                    mma_fp16(acc[mi][2 * njp],     af[mi], bf[0], bf[1]);
                    mma_fp16(acc[mi][2 * njp + 1], af[mi], bf[2], bf[3]);
                }
            }
        }
        __syncthreads();
        stg = (stg + 1) % 3;
    }

    // ---- epilogue ----
#pragma unroll
    for (int mi = 0; mi < 4; mi++) {
        int row0 = m0 + wm + mi * 16 + grp;
#pragma unroll
        for (int nj = 0; nj < 4; nj++) {
            int col = n0 + wn + nj * 8 + qid * 2;
            if (MODE == 0) {
                *(float2*)(C + (size_t)row0 * N + col) =
                    make_float2(acc[mi][nj][0], acc[mi][nj][1]);
                *(float2*)(C + (size_t)(row0 + 8) * N + col) =
                    make_float2(acc[mi][nj][2], acc[mi][nj][3]);
            } else {
                const int d2 = (col >> 1) & 63;
#pragma unroll
                for (int half = 0; half < 2; half++) {
                    int r = row0 + half * 8;
                    float x0 = acc[mi][nj][half * 2];
                    float x1 = acc[mi][nj][half * 2 + 1];
                    int s = r & (S_ - 1);
                    float cc = cs[s * 64 + d2];
                    float sv = sn[s * 64 + d2];
                    float o0 = x0 * cc - x1 * sv;
                    float o1 = x0 * sv + x1 * cc;
                    if (MODE == 1) {
                        // 1/sqrt(128) * log2(e): logits emerge in log2 domain
                        const float scale = 0.08838834764831845f * 1.4426950408889634f;
                        o0 *= scale; o1 *= scale;
                    }
                    size_t o;
                    if (MODE == 1) o = (size_t)r * DP_ + (col >> 1);
                    else {
                        int b = r >> 11, ss = r & (S_ - 1), hk = col >> 7;
                        o = ((size_t)(b * HK_ + hk) * S_ + ss) * 64 + d2;
                    }
                    O16[o] = packh2(o0, o1);
                }
            }
        }
    }
}

// =====================================================================
// Flash attention: fp16 MMA, log2-domain h2exp2 softmax, ones-column l.
// BM=128, BN=128 (halved tile count), 2-stage cp.async, 1 CTA/SM.
// 256 threads = 8 warps; qt reversed for tail packing.
// =====================================================================
#define KSTR 68                          // K row stride (u32): 64 data + 4 pad
#define VSTR 68                          // Vt/P row stride (u32): 64 data + 4 pad
#define VROWS 136                        // 128 d-rows + ones row + 7 zero rows
#define KPLU (128 * KSTR)                // 8704 u32
#define VPLU (VROWS * VSTR)              // 9248 u32
#define ASTGU (KPLU + VPLU)              // 17952 u32 per stage
#define PPLU (128 * VSTR)                // 8704 u32 (P tile)
#define A_SMEM ((2 * ASTGU + PPLU) * 4)  // 178432 B -> 1 CTA/SM

__global__ void __launch_bounds__(256, 1) attn_mma(const unsigned* __restrict__ Q16,
                                                   const unsigned* __restrict__ K16,
                                                   const unsigned* __restrict__ Vt16,
                                                   unsigned* __restrict__ Of16)
{
    extern __shared__ unsigned smu[];
    const unsigned sm_base = s2u(smu);
    unsigned* Ps = smu + 2 * ASTGU;
    const unsigned pbb = sm_base + (unsigned)(2 * ASTGU * 4);

    const int tid  = threadIdx.x;
    const int lane = tid & 31;
    const int warp = tid >> 5;
    const int grp  = lane >> 2;
    const int qid  = lane & 3;
    const int qt = (S_ / 128 - 1) - blockIdx.x;   // longest CTAs first
    const int h  = blockIdx.y;
    const int b  = blockIdx.z;
    const int hk = h >> 2;
    const int q0  = qt * 128;
    const int wq0 = warp * 16;

    const unsigned* kb = K16  + (size_t)(b * HK_ + hk) * S_ * 64;
    const unsigned* vb = Vt16 + (size_t)(b * HK_ + hk) * HD_ * SP_;

    const unsigned koff = (unsigned)(((lane >> 4) * 8 + (lane & 7)) * KSTR * 4
                                     + ((lane >> 3) & 1) * 16);
    const unsigned voff = (unsigned)(((lane >> 4) * 8 + (lane & 7)) * VSTR * 4
                                     + ((lane >> 3) & 1) * 16);
    const unsigned poff = (unsigned)((wq0 + (lane & 15)) * VSTR * 4 + (lane >> 4) * 16);
    const int la = lane & 15;
    const unsigned loff = (unsigned)((128 + (la & 7)) * VSTR * 4 + (la >> 3) * 16);

    // init constant ones/zero rows 128..135 in both stages (cp.async never touches them)
    for (int i = tid; i < 2 * 8 * VSTR; i += 256) {
        int stg = i / (8 * VSTR);
        int rem = i - stg * (8 * VSTR);
        int rr  = rem / VSTR;
        int cc  = rem - rr * VSTR;
        smu[stg * ASTGU + KPLU + (128 + rr) * VSTR + cc] = (rr == 0) ? 0x3C003C00u : 0u;
    }

    unsigned qf[8][4];
    {
        const unsigned* qp = Q16 + (size_t)(b * S_ + q0 + wq0) * DP_ + h * 64;
#pragma unroll
        for (int kk = 0; kk < 8; kk++) {
            qf[kk][0] = qp[(size_t)grp * DP_ + kk * 8 + qid];
            qf[kk][1] = qp[(size_t)(grp + 8) * DP_ + kk * 8 + qid];
            qf[kk][2] = qp[(size_t)grp * DP_ + kk * 8 + qid + 4];
            qf[kk][3] = qp[(size_t)(grp + 8) * DP_ + kk * 8 + qid + 4];
        }
    }

    float o_acc[16][4];
#pragma unroll
    for (int i = 0; i < 16; i++)
#pragma unroll
        for (int c = 0; c < 4; c++) o_acc[i][c] = 0.0f;
    float o_l[4] = {0.0f, 0.0f, 0.0f, 0.0f};
    float m0r = -1e30f, m1r = -1e30f;

    const int qrow0 = q0 + wq0 + grp;
    const int tmax = qt;

    // cp.async geometry: K rows 0..127 (2 threads/row, 8x16B each);
    // V rows 0..127 likewise.
    const int krr = tid >> 1;
    const int khalf = tid & 1;

    auto issueT = [&](int tt, int stg) {
        const unsigned sb = sm_base + (unsigned)(stg * ASTGU * 4);
        const int kv = tt * 128;
        const unsigned* gk = kb + (size_t)(kv + krr) * 64 + khalf * 32;
        const unsigned ks = sb + krr * (KSTR * 4) + khalf * 128;
#pragma unroll
        for (int j = 0; j < 8; j++) cpa16(ks + j * 16, gk + j * 4);
        const unsigned* gv = vb + (size_t)krr * SP_ + (kv >> 1) + khalf * 32;
        const unsigned vs = sb + KPLU * 4 + krr * (VSTR * 4) + khalf * 128;
#pragma unroll
        for (int j = 0; j < 8; j++) cpa16(vs + j * 16, gv + j * 4);
        asm volatile("cp.async.commit_group;");
    };

    issueT(0, 0);

    for (int t = 0; t <= tmax; t++) {
        const int kv0 = t * 128;
        if (t < tmax) {
            issueT(t + 1, (t + 1) & 1);
            asm volatile("cp.async.wait_group 1;");
        } else {
            asm volatile("cp.async.wait_group 0;");
        }
        __syncthreads();

        const unsigned skh = sm_base + (unsigned)((t & 1) * ASTGU * 4);
        const unsigned svh = skh + (unsigned)(KPLU * 4);

        // ---- S = Q K^T (log2-domain logits) ----
        float s[16][4];
#pragma unroll
        for (int nj = 0; nj < 16; nj++)
#pragma unroll
            for (int c = 0; c < 4; c++) s[nj][c] = 0.0f;

#pragma unroll
        for (int kk = 0; kk < 8; kk++) {
#pragma unroll
            for (int njp = 0; njp < 8; njp++) {
                unsigned bf[4];
                ldsm4(bf, skh + koff + njp * (16 * KSTR * 4) + kk * 32);
                mma_fp16(s[2 * njp],     qf[kk], bf[0], bf[1]);
                mma_fp16(s[2 * njp + 1], qf[kk], bf[2], bf[3]);
            }
        }

        // causal mask (only the diagonal tile crosses)
        if (kv0 + 127 > q0 + wq0) {
#pragma unroll
            for (int nj = 0; nj < 16; nj++) {
                int kcol = kv0 + nj * 8 + 2 * qid;
                if (kcol     > qrow0)     s[nj][0] = -1e30f;
                if (kcol + 1 > qrow0)     s[nj][1] = -1e30f;
                if (kcol     > qrow0 + 8) s[nj][2] = -1e30f;
                if (kcol + 1 > qrow0 + 8) s[nj][3] = -1e30f;
            }
        }

        // ---- online softmax: max reduce (fp32), P via h2exp2 ----
        float rm0 = -1e30f, rm1 = -1e30f;
#pragma unroll
        for (int nj = 0; nj < 16; nj++) {
            rm0 = fmaxf(rm0, fmaxf(s[nj][0], s[nj][1]));
            rm1 = fmaxf(rm1, fmaxf(s[nj][2], s[nj][3]));
        }
        rm0 = fmaxf(rm0, __shfl_xor_sync(0xffffffffu, rm0, 1));
        rm0 = fmaxf(rm0, __shfl_xor_sync(0xffffffffu, rm0, 2));
        rm1 = fmaxf(rm1, __shfl_xor_sync(0xffffffffu, rm1, 1));
        rm1 = fmaxf(rm1, __shfl_xor_sync(0xffffffffu, rm1, 2));

        float mn0 = fmaxf(m0r, rm0), mn1 = fmaxf(m1r, rm1);
        float a0 = exp2f(m0r - mn0), a1 = exp2f(m1r - mn1);
        m0r = mn0; m1r = mn1;

#pragma unroll
        for (int nj = 0; nj < 16; nj++) {
            __half2 p0 = h2exp2(__floats2half2_rn(s[nj][0] - mn0, s[nj][1] - mn0));
            Ps[(wq0 + grp) * VSTR + nj * 4 + qid] = *reinterpret_cast<unsigned*>(&p0);
            __half2 p1 = h2exp2(__floats2half2_rn(s[nj][2] - mn1, s[nj][3] - mn1));
            Ps[(wq0 + grp + 8) * VSTR + nj * 4 + qid] = *reinterpret_cast<unsigned*>(&p1);
        }

#pragma unroll
        for (int nj = 0; nj < 16; nj++) {
            o_acc[nj][0] *= a0; o_acc[nj][1] *= a0;
            o_acc[nj][2] *= a1; o_acc[nj][3] *= a1;
        }
        o_l[0] *= a0; o_l[1] *= a0; o_l[2] *= a1; o_l[3] *= a1;
        __syncwarp();

        // ---- O += P V ; l += P * ones ----
#pragma unroll
        for (int kk = 0; kk < 8; kk++) {
            unsigned pa[4];
            ldsm4(pa, pbb + poff + kk * 32);
#pragma unroll
            for (int njp = 0; njp < 8; njp++) {
                unsigned vf[4];
                ldsm4(vf, svh + voff + njp * (16 * VSTR * 4) + kk * 32);
                mma_fp16(o_acc[2 * njp],     pa, vf[0], vf[1]);
                mma_fp16(o_acc[2 * njp + 1], pa, vf[2], vf[3]);
            }
            unsigned lf[2];
            ldsm2(lf, svh + loff + kk * 32);
            mma_fp16(o_l, pa, lf[0], lf[1]);
        }
        __syncthreads();
    }

    // l lives in column 0 of the ones-MMA output: qid==0 lanes hold it
    const int src = lane & ~3;
    const float l0 = __shfl_sync(0xffffffffu, o_l[0], src);
    const float l1 = __shfl_sync(0xffffffffu, o_l[2], src);
    const float il0 = 1.0f / l0;
    const float il1 = 1.0f / l1;
    const size_t r0 = (size_t)(b * S_ + q0 + wq0 + grp) * DP_;
    const size_t r1 = (size_t)(b * S_ + q0 + wq0 + grp + 8) * DP_;
#pragma unroll
    for (int nj = 0; nj < 16; nj++) {
        int col = h * 64 + nj * 4 + qid;
        Of16[r0 + col] = packh2(o_acc[nj][0] * il0, o_acc[nj][1] * il0);
        Of16[r1 + col] = packh2(o_acc[nj][2] * il1, o_acc[nj][3] * il1);
    }
}

// =====================================================================
// launch
// =====================================================================
extern "C" void kernel_launch(void* const* d_in, const int* in_sizes, int n_in,
                              void* d_out, int out_size)
{
    const float* x  = (const float*)d_in[0];
    const float* fc = (const float*)d_in[1];
    const float* fs = (const float*)d_in[2];
    const float* wq = (const float*)d_in[3];
    const float* wk = (const float*)d_in[4];
    const float* wv = (const float*)d_in[5];
    const float* wo = (const float*)d_in[6];
    float* out = (float*)d_out;

    float *v;
    unsigned *x16, *wq16, *wk16, *wv16, *wo16, *af16, *q16, *k16, *vt16;
    cudaGetSymbolAddress((void**)&v,    g_v);
    cudaGetSymbolAddress((void**)&x16,  g_x16);
    cudaGetSymbolAddress((void**)&wq16, g_wq16);
    cudaGetSymbolAddress((void**)&wk16, g_wk16);
    cudaGetSymbolAddress((void**)&wv16, g_wv16);
    cudaGetSymbolAddress((void**)&wo16, g_wo16);
    cudaGetSymbolAddress((void**)&af16, g_af16);
    cudaGetSymbolAddress((void**)&q16,  g_q16);
    cudaGetSymbolAddress((void**)&k16,  g_k16);
    cudaGetSymbolAddress((void**)&vt16, g_vt16);

    // fp16 packs
    {
        int np;
        np = M_ * DP_;   pack16_kernel<<<np / 256, 256>>>(x,  x16,  np);
        np = D_ * DP_;   pack16_kernel<<<np / 256, 256>>>(wq, wq16, np);
        np = KVD_ * DP_; pack16_kernel<<<np / 256, 256>>>(wk, wk16, np);
        np = KVD_ * DP_; pack16_kernel<<<np / 256, 256>>>(wv, wv16, np);
        np = D_ * DP_;   pack16_kernel<<<np / 256, 256>>>(wo, wo16, np);
    }

    cudaFuncSetAttribute(gemm16<0>, cudaFuncAttributeMaxDynamicSharedMemorySize, G_SMEM);
    cudaFuncSetAttribute(gemm16<1>, cudaFuncAttributeMaxDynamicSharedMemorySize, G_SMEM);
    cudaFuncSetAttribute(gemm16<2>, cudaFuncAttributeMaxDynamicSharedMemorySize, G_SMEM);

    // projections (fp16 single-stream; Q scaled into log2 domain, K roped)
    gemm16<1><<<dim3(32, 16), 512, G_SMEM>>>(x16, wq16, nullptr, q16, fc, fs, D_, D_);
    gemm16<2><<<dim3(8,  16), 512, G_SMEM>>>(x16, wk16, nullptr, k16, fc, fs, KVD_, D_);
    gemm16<0><<<dim3(8,  16), 512, G_SMEM>>>(x16, wv16, v, nullptr, nullptr, nullptr, KVD_, D_);

    // V transpose+pack (fp16 plane)
    transpose_pack_v<<<dim3(S_ / 64, HK_, B_), 256>>>(v, vt16);

    // attention (fp16 MMA, BN=128 tiles, h2exp2, ones-column denominator)
    cudaFuncSetAttribute(attn_mma, cudaFuncAttributeMaxDynamicSharedMemorySize, A_SMEM);
    attn_mma<<<dim3(S_ / 128, H_, B_), 256, A_SMEM>>>(q16, k16, vt16, af16);

    // output projection (fp16 single-stream)
    gemm16<0><<<dim3(32, 16), 512, G_SMEM>>>(af16, wo16, out, nullptr, nullptr, nullptr, D_, D_);
}

// round 15
// speedup vs baseline: 1.0587x; 1.0587x over previous
#include <cuda_runtime.h>
#include <cuda_bf16.h>
#include <cuda_fp16.h>
#include <cstdint>
#include <math.h>

#define B_   2
#define S_   2048
#define D_   4096
#define H_   32
#define HK_  8
#define HD_  128
#define M_   (B_ * S_)          // 4096 total tokens
#define KVD_ (HK_ * HD_)        // 1024
#define DP_  (D_ / 2)           // 2048 u32 pairs per row
#define SP_  (S_ / 2)           // 1024 seq pairs

// ---------------- scratch (device globals; no allocation allowed) ----------------
__device__ float    g_v[(size_t)M_ * KVD_];
// fp16 packed pair planes
__device__ unsigned g_x16[(size_t)M_ * DP_];
__device__ unsigned g_wq16[(size_t)D_ * DP_];
__device__ unsigned g_wk16[(size_t)KVD_ * DP_];
__device__ unsigned g_wv16[(size_t)KVD_ * DP_];
__device__ unsigned g_wo16[(size_t)D_ * DP_];
__device__ unsigned g_af16[(size_t)M_ * DP_];   // attention out (fp16 pairs)
__device__ unsigned g_q16[(size_t)M_ * DP_];                  // roped+scaled(log2e) Q (fp16)
__device__ unsigned g_k16[(size_t)B_ * HK_ * S_ * 64];        // roped K [b,hk,s,64]
__device__ unsigned g_vt16[(size_t)B_ * HK_ * HD_ * SP_];     // V^T [b,hk,d,s-pairs]

// ---------------- helpers ----------------
__device__ __forceinline__ unsigned packh2(float x, float y) {
    __half2 h = __floats2half2_rn(x, y);
    return *reinterpret_cast<unsigned*>(&h);
}

__device__ __forceinline__ void mma_fp16(float* c, const unsigned* a, unsigned b0, unsigned b1) {
    asm volatile(
        "mma.sync.aligned.m16n8k16.row.col.f32.f16.f16.f32 "
        "{%0,%1,%2,%3}, {%4,%5,%6,%7}, {%8,%9}, {%0,%1,%2,%3};\n"
        : "+f"(c[0]), "+f"(c[1]), "+f"(c[2]), "+f"(c[3])
        : "r"(a[0]), "r"(a[1]), "r"(a[2]), "r"(a[3]), "r"(b0), "r"(b1));
}

__device__ __forceinline__ void cpa16(unsigned saddr, const void* g) {
    asm volatile("cp.async.cg.shared.global [%0], [%1], 16;" :: "r"(saddr), "l"(g));
}

__device__ __forceinline__ uint32_t s2u(const void* p) {
    uint32_t a;
    asm("{ .reg .u64 t; cvta.to.shared.u64 t, %1; cvt.u32.u64 %0, t; }" : "=r"(a) : "l"(p));
    return a;
}

__device__ __forceinline__ void ldsm4(unsigned* r, uint32_t a) {
    asm volatile("ldmatrix.sync.aligned.m8n8.x4.shared.b16 {%0,%1,%2,%3}, [%4];"
                 : "=r"(r[0]), "=r"(r[1]), "=r"(r[2]), "=r"(r[3]) : "r"(a));
}

__device__ __forceinline__ void ldsm2(unsigned* r, uint32_t a) {
    asm volatile("ldmatrix.sync.aligned.m8n8.x2.shared.b16 {%0,%1}, [%2];"
                 : "=r"(r[0]), "=r"(r[1]) : "r"(a));
}

// ---------------- pack pass: fp32 -> fp16 pair plane ----------------
__global__ void pack16_kernel(const float* __restrict__ X,
                              unsigned* __restrict__ O, int npairs)
{
    int i = blockIdx.x * blockDim.x + threadIdx.x;
    if (i >= npairs) return;
    float2 v = ((const float2*)X)[i];
    O[i] = packh2(v.x, v.y);
}

// ---------------- transpose + pack V -> fp16 plane [b,hk,d,s-pairs] ----------------
__global__ void __launch_bounds__(256) transpose_pack_v(const float* __restrict__ V,
                                                        unsigned* __restrict__ O)
{
    __shared__ float sm[64 * 132];
    const int tid = threadIdx.x;
    const int s0  = blockIdx.x * 64;
    const int hk  = blockIdx.y;
    const int b   = blockIdx.z;

#pragma unroll
    for (int i = 0; i < 32; i++) {
        int idx = tid + i * 256;
        int r = idx >> 7, c = idx & 127;
        sm[r * 132 + c] = V[(size_t)(b * S_ + s0 + r) * KVD_ + hk * HD_ + c];
    }
    __syncthreads();

    const int d  = tid >> 1;
    const int pb = (tid & 1) * 16;
    unsigned* o = O + ((size_t)(b * HK_ + hk) * HD_ + d) * SP_ + (s0 >> 1) + pb;
#pragma unroll
    for (int i = 0; i < 16; i++) {
        int p = pb + i;
        o[i] = packh2(sm[(2 * p) * 132 + d], sm[(2 * p + 1) * 132 + d]);
    }
}

// =====================================================================
// fp16 single-stream GEMM (ldmatrix fragments):
// C[M,N] = A[M,K]*B[N,K]^T, CTA tile 128x128, BK=64, 256 threads,
// 8 warps of 64x32, 3-stage cp.async, 2 CTAs/SM co-resident.
// MODE 0: fp32 C. MODE 1: rope+scale*log2e -> fp16 Q plane [row][DP_].
// MODE 2: rope -> fp16 K plane [b,hk,s,64].
// =====================================================================
#define GSTR 36                       // smem row stride (u32): 32 data + 4 pad
#define APLU (128 * GSTR)             // 4608 u32
#define BPLU (128 * GSTR)             // 4608 u32
#define GSTGU (APLU + BPLU)           // 9216 u32 per stage
#define G_SMEM (3 * GSTGU * 4)        // 110592 B -> 2 CTAs/SM

template <int MODE>
__global__ void __launch_bounds__(256, 2)
gemm16(const unsigned* __restrict__ Ap, const unsigned* __restrict__ Bp,
       float* __restrict__ C, unsigned* __restrict__ O16,
       const float* __restrict__ cs, const float* __restrict__ sn,
       int N, int K)
{
    extern __shared__ unsigned gs[];

    const int tid  = threadIdx.x;
    const int lane = tid & 31;
    const int warp = tid >> 5;
    const int m0 = blockIdx.y << 7;
    const int n0 = blockIdx.x << 7;
    const int wm = (warp >> 2) * 64;
    const int wn = (warp & 3) * 32;
    const int grp = lane >> 2;
    const int qid = lane & 3;
    const int KP = K >> 1;

    // cp.async mapping: A rows 0..127, B rows 0..127; 2 threads/row, 64B halves
    const int lr  = tid >> 1;
    const int lc  = (tid & 1) * 16;
    const unsigned* ag = Ap + (size_t)(m0 + lr) * KP + lc;
    const unsigned* bg = Bp + (size_t)(n0 + lr) * KP + lc;

    const unsigned sbase = s2u(gs);
    const unsigned sr = (lr * GSTR + lc) * 4;

    const unsigned aoff = (unsigned)((wm + (lane & 15)) * GSTR * 4 + (lane >> 4) * 16);
    const unsigned boff = (unsigned)((wn + (lane >> 4) * 8 + (lane & 7)) * GSTR * 4
                                     + ((lane >> 3) & 1) * 16);

    float acc[4][4][4];
#pragma unroll
    for (int i = 0; i < 4; i++)
#pragma unroll
        for (int j = 0; j < 4; j++)
#pragma unroll
            for (int c = 0; c < 4; c++) acc[i][j][c] = 0.0f;

    const int nch = K / 64;

    auto issue = [&](int c, int stg) {
        unsigned sb = sbase + (unsigned)(stg * GSTGU * 4);
        const int go = c * 32;
        cpa16(sb + sr,                ag + go);
        cpa16(sb + sr + 16,           ag + go + 4);
        cpa16(sb + sr + 32,           ag + go + 8);
        cpa16(sb + sr + 48,           ag + go + 12);
        cpa16(sb + APLU * 4 + sr,      bg + go);
        cpa16(sb + APLU * 4 + sr + 16, bg + go + 4);
        cpa16(sb + APLU * 4 + sr + 32, bg + go + 8);
        cpa16(sb + APLU * 4 + sr + 48, bg + go + 12);
        asm volatile("cp.async.commit_group;");
    };

    issue(0, 0);
    if (nch > 1) issue(1, 1);

    int stg = 0;
    for (int c = 0; c < nch; c++) {
        if (c + 2 < nch) issue(c + 2, (stg + 2) % 3);
        const int rem = nch - 1 - c;
        if (rem >= 2)      { asm volatile("cp.async.wait_group 2;"); }
        else if (rem == 1) { asm volatile("cp.async.wait_group 1;"); }
        else               { asm volatile("cp.async.wait_group 0;"); }
        __syncthreads();

        const unsigned sA = sbase + (unsigned)(stg * GSTGU * 4);
        const unsigned sB = sA + APLU * 4;

#pragma unroll
        for (int kk = 0; kk < 4; kk++) {
            unsigned af[4][4];
#pragma unroll
            for (int mi = 0; mi < 4; mi++)
                ldsm4(af[mi], sA + aoff + mi * (16 * GSTR * 4) + kk * 32);
#pragma unroll
            for (int njp = 0; njp < 2; njp++) {
                unsigned bf[4];
                ldsm4(bf, sB + boff + njp * (16 * GSTR * 4) + kk * 32);
#pragma unroll
                for (int mi = 0; mi < 4; mi++) {
                    mma_fp16(acc[mi][2 * njp],     af[mi], bf[0], bf[1]);
                    mma_fp16(acc[mi][2 * njp + 1], af[mi], bf[2], bf[3]);
                }
            }
        }
        __syncthreads();
        stg = (stg + 1) % 3;
    }

    // ---- epilogue ----
#pragma unroll
    for (int mi = 0; mi < 4; mi++) {
        int row0 = m0 + wm + mi * 16 + grp;
#pragma unroll
        for (int nj = 0; nj < 4; nj++) {
            int col = n0 + wn + nj * 8 + qid * 2;
            if (MODE == 0) {
                *(float2*)(C + (size_t)row0 * N + col) =
                    make_float2(acc[mi][nj][0], acc[mi][nj][1]);
                *(float2*)(C + (size_t)(row0 + 8) * N + col) =
                    make_float2(acc[mi][nj][2], acc[mi][nj][3]);
            } else {
                const int d2 = (col >> 1) & 63;
#pragma unroll
                for (int half = 0; half < 2; half++) {
                    int r = row0 + half * 8;
                    float x0 = acc[mi][nj][half * 2];
                    float x1 = acc[mi][nj][half * 2 + 1];
                    int s = r & (S_ - 1);
                    float cc = cs[s * 64 + d2];
                    float sv = sn[s * 64 + d2];
                    float o0 = x0 * cc - x1 * sv;
                    float o1 = x0 * sv + x1 * cc;
                    if (MODE == 1) {
                        // 1/sqrt(128) * log2(e): logits emerge in log2 domain
                        const float scale = 0.08838834764831845f * 1.4426950408889634f;
                        o0 *= scale; o1 *= scale;
                    }
                    size_t o;
                    if (MODE == 1) o = (size_t)r * DP_ + (col >> 1);
                    else {
                        int b = r >> 11, ss = r & (S_ - 1), hk = col >> 7;
                        o = ((size_t)(b * HK_ + hk) * S_ + ss) * 64 + d2;
                    }
                    O16[o] = packh2(o0, o1);
                }
            }
        }
    }
}

// =====================================================================
// Flash attention (R13 config): fp16 MMA, log2-domain h2exp2 softmax,
// ones-column denominator. BM=128, BN=64, 3-stage, 1 CTA/SM.
// LPT: longest CTAs (high qt) launch first.
// =====================================================================
#define KSTR 68                          // K row stride (u32): 64 + 4
#define VSTR 36                          // Vt/P row stride (u32): 32 + 4
#define VROWS 136                        // 128 d-rows + ones row + 7 zero rows
#define KPLU (64 * KSTR)                 // 4352 u32
#define VPLU (VROWS * VSTR)              // 4896 u32
#define ASTGU (KPLU + VPLU)              // 9248 u32 per stage
#define PPLU (128 * VSTR)                // 4608 u32 (P tile)
#define A_SMEM ((3 * ASTGU + PPLU) * 4)  // 129408 B -> 1 CTA/SM

__global__ void __launch_bounds__(256, 1) attn_mma(const unsigned* __restrict__ Q16,
                                                   const unsigned* __restrict__ K16,
                                                   const unsigned* __restrict__ Vt16,
                                                   unsigned* __restrict__ Of16)
{
    extern __shared__ unsigned smu[];
    const unsigned sm_base = s2u(smu);
    unsigned* Ps = smu + 3 * ASTGU;
    const unsigned pbb = sm_base + (unsigned)(3 * ASTGU * 4);

    const int tid  = threadIdx.x;
    const int lane = tid & 31;
    const int warp = tid >> 5;
    const int grp  = lane >> 2;
    const int qid  = lane & 3;
    const int qt = (S_ / 128 - 1) - blockIdx.x;   // LPT: longest first
    const int h  = blockIdx.y;
    const int b  = blockIdx.z;
    const int hk = h >> 2;
    const int q0  = qt * 128;
    const int wq0 = warp * 16;

    const unsigned* kb = K16  + (size_t)(b * HK_ + hk) * S_ * 64;
    const unsigned* vb = Vt16 + (size_t)(b * HK_ + hk) * HD_ * SP_;

    const unsigned koff = (unsigned)(((lane >> 4) * 8 + (lane & 7)) * KSTR * 4
                                     + ((lane >> 3) & 1) * 16);
    const unsigned voff = (unsigned)(((lane >> 4) * 8 + (lane & 7)) * VSTR * 4
                                     + ((lane >> 3) & 1) * 16);
    const unsigned poff = (unsigned)((wq0 + (lane & 15)) * VSTR * 4 + (lane >> 4) * 16);
    const int la = lane & 15;
    const unsigned loff = (unsigned)((128 + (la & 7)) * VSTR * 4 + (la >> 3) * 16);

    // init constant ones/zero rows 128..135 in all 3 stages (cp.async never touches them)
    for (int i = tid; i < 3 * 8 * 32; i += 256) {
        int stg = i / 256;
        int rr  = (i >> 5) & 7;
        int cc  = i & 31;
        smu[stg * ASTGU + KPLU + (128 + rr) * VSTR + cc] = (rr == 0) ? 0x3C003C00u : 0u;
    }

    unsigned qf[8][4];
    {
        const unsigned* qp = Q16 + (size_t)(b * S_ + q0 + wq0) * DP_ + h * 64;
#pragma unroll
        for (int kk = 0; kk < 8; kk++) {
            qf[kk][0] = qp[(size_t)grp * DP_ + kk * 8 + qid];
            qf[kk][1] = qp[(size_t)(grp + 8) * DP_ + kk * 8 + qid];
            qf[kk][2] = qp[(size_t)grp * DP_ + kk * 8 + qid + 4];
            qf[kk][3] = qp[(size_t)(grp + 8) * DP_ + kk * 8 + qid + 4];
        }
    }

    float o_acc[16][4];
#pragma unroll
    for (int i = 0; i < 16; i++)
#pragma unroll
        for (int c = 0; c < 4; c++) o_acc[i][c] = 0.0f;
    float o_l[4] = {0.0f, 0.0f, 0.0f, 0.0f};
    float m0r = -1e30f, m1r = -1e30f;

    const int qrow0 = q0 + wq0 + grp;
    const int tmax = 2 * qt + 1;

    const int krr = tid >> 2;
    const int kcc = tid & 3;
    const int vrr = tid >> 1;
    const int vcc = tid & 1;

    auto issueT = [&](int tt, int stg) {
        const unsigned sb = sm_base + (unsigned)(stg * ASTGU * 4);
        const int kv = tt * 64;
        const unsigned* gk = kb + (size_t)(kv + krr) * 64 + kcc * 4;
        const unsigned ks = sb + krr * (KSTR * 4) + kcc * 16;
#pragma unroll
        for (int j = 0; j < 4; j++) cpa16(ks + j * 64, gk + j * 16);
        const unsigned* gv = vb + (size_t)vrr * SP_ + (kv >> 1) + vcc * 4;
        const unsigned vs = sb + KPLU * 4 + vrr * (VSTR * 4) + vcc * 16;
#pragma unroll
        for (int j = 0; j < 4; j++) cpa16(vs + j * 32, gv + j * 8);
        asm volatile("cp.async.commit_group;");
    };

    issueT(0, 0);
    if (tmax >= 1) issueT(1, 1);

    int stg = 0;
    for (int t = 0; t <= tmax; t++) {
        const int kv0 = t * 64;
        if (t + 2 <= tmax) issueT(t + 2, (stg + 2) % 3);
        const int rem = tmax - t;
        if (rem >= 2)      { asm volatile("cp.async.wait_group 2;"); }
        else if (rem == 1) { asm volatile("cp.async.wait_group 1;"); }
        else               { asm volatile("cp.async.wait_group 0;"); }
        __syncthreads();

        if (kv0 <= q0 + wq0 + 15) {
            const unsigned skh = sm_base + (unsigned)(stg * ASTGU * 4);
            const unsigned svh = skh + (unsigned)(KPLU * 4);

            // ---- S = Q K^T (log2-domain logits) ----
            float s[8][4];
#pragma unroll
            for (int nj = 0; nj < 8; nj++)
#pragma unroll
                for (int c = 0; c < 4; c++) s[nj][c] = 0.0f;

#pragma unroll
            for (int kk = 0; kk < 8; kk++) {
#pragma unroll
                for (int njp = 0; njp < 4; njp++) {
                    unsigned bf[4];
                    ldsm4(bf, skh + koff + njp * (16 * KSTR * 4) + kk * 32);
                    mma_fp16(s[2 * njp],     qf[kk], bf[0], bf[1]);
                    mma_fp16(s[2 * njp + 1], qf[kk], bf[2], bf[3]);
                }
            }

            if (kv0 + 63 > q0 + wq0) {
#pragma unroll
                for (int nj = 0; nj < 8; nj++) {
                    int kcol = kv0 + nj * 8 + 2 * qid;
                    if (kcol     > qrow0)     s[nj][0] = -1e30f;
                    if (kcol + 1 > qrow0)     s[nj][1] = -1e30f;
                    if (kcol     > qrow0 + 8) s[nj][2] = -1e30f;
                    if (kcol + 1 > qrow0 + 8) s[nj][3] = -1e30f;
                }
            }

            // ---- online softmax: max reduce (fp32), P via h2exp2 ----
            float rm0 = -1e30f, rm1 = -1e30f;
#pragma unroll
            for (int nj = 0; nj < 8; nj++) {
                rm0 = fmaxf(rm0, fmaxf(s[nj][0], s[nj][1]));
                rm1 = fmaxf(rm1, fmaxf(s[nj][2], s[nj][3]));
            }
            rm0 = fmaxf(rm0, __shfl_xor_sync(0xffffffffu, rm0, 1));
            rm0 = fmaxf(rm0, __shfl_xor_sync(0xffffffffu, rm0, 2));
            rm1 = fmaxf(rm1, __shfl_xor_sync(0xffffffffu, rm1, 1));
            rm1 = fmaxf(rm1, __shfl_xor_sync(0xffffffffu, rm1, 2));

            float mn0 = fmaxf(m0r, rm0), mn1 = fmaxf(m1r, rm1);
            float a0 = exp2f(m0r - mn0), a1 = exp2f(m1r - mn1);
            m0r = mn0; m1r = mn1;

#pragma unroll
            for (int nj = 0; nj < 8; nj++) {
                __half2 p0 = h2exp2(__floats2half2_rn(s[nj][0] - mn0, s[nj][1] - mn0));
                Ps[(wq0 + grp) * VSTR + nj * 4 + qid] = *reinterpret_cast<unsigned*>(&p0);
                __half2 p1 = h2exp2(__floats2half2_rn(s[nj][2] - mn1, s[nj][3] - mn1));
                Ps[(wq0 + grp + 8) * VSTR + nj * 4 + qid] = *reinterpret_cast<unsigned*>(&p1);
            }

#pragma unroll
            for (int nj = 0; nj < 16; nj++) {
                o_acc[nj][0] *= a0; o_acc[nj][1] *= a0;
                o_acc[nj][2] *= a1; o_acc[nj][3] *= a1;
            }
            o_l[0] *= a0; o_l[1] *= a0; o_l[2] *= a1; o_l[3] *= a1;
            __syncwarp();

            // ---- O += P V ; l += P * ones (extra row) ----
#pragma unroll
            for (int kk = 0; kk < 4; kk++) {
                unsigned pa[4];
                ldsm4(pa, pbb + poff + kk * 32);
#pragma unroll
                for (int njp = 0; njp < 8; njp++) {
                    unsigned vf[4];
                    ldsm4(vf, svh + voff + njp * (16 * VSTR * 4) + kk * 32);
                    mma_fp16(o_acc[2 * njp],     pa, vf[0], vf[1]);
                    mma_fp16(o_acc[2 * njp + 1], pa, vf[2], vf[3]);
                }
                unsigned lf[2];
                ldsm2(lf, svh + loff + kk * 32);
                mma_fp16(o_l, pa, lf[0], lf[1]);
            }
        }
        __syncthreads();
        stg = (stg + 1) % 3;
    }

    // l lives in column 0 of the ones-MMA output: qid==0 lanes hold it
    const int src = lane & ~3;
    const float l0 = __shfl_sync(0xffffffffu, o_l[0], src);
    const float l1 = __shfl_sync(0xffffffffu, o_l[2], src);
    const float il0 = 1.0f / l0;
    const float il1 = 1.0f / l1;
    const size_t r0 = (size_t)(b * S_ + q0 + wq0 + grp) * DP_;
    const size_t r1 = (size_t)(b * S_ + q0 + wq0 + grp + 8) * DP_;
#pragma unroll
    for (int nj = 0; nj < 16; nj++) {
        int col = h * 64 + nj * 4 + qid;
        Of16[r0 + col] = packh2(o_acc[nj][0] * il0, o_acc[nj][1] * il0);
        Of16[r1 + col] = packh2(o_acc[nj][2] * il1, o_acc[nj][3] * il1);
    }
}

// =====================================================================
// launch
// =====================================================================
extern "C" void kernel_launch(void* const* d_in, const int* in_sizes, int n_in,
                              void* d_out, int out_size)
{
    const float* x  = (const float*)d_in[0];
    const float* fc = (const float*)d_in[1];
    const float* fs = (const float*)d_in[2];
    const float* wq = (const float*)d_in[3];
    const float* wk = (const float*)d_in[4];
    const float* wv = (const float*)d_in[5];
    const float* wo = (const float*)d_in[6];
    float* out = (float*)d_out;

    float *v;
    unsigned *x16, *wq16, *wk16, *wv16, *wo16, *af16, *q16, *k16, *vt16;
    cudaGetSymbolAddress((void**)&v,    g_v);
    cudaGetSymbolAddress((void**)&x16,  g_x16);
    cudaGetSymbolAddress((void**)&wq16, g_wq16);
    cudaGetSymbolAddress((void**)&wk16, g_wk16);
    cudaGetSymbolAddress((void**)&wv16, g_wv16);
    cudaGetSymbolAddress((void**)&wo16, g_wo16);
    cudaGetSymbolAddress((void**)&af16, g_af16);
    cudaGetSymbolAddress((void**)&q16,  g_q16);
    cudaGetSymbolAddress((void**)&k16,  g_k16);
    cudaGetSymbolAddress((void**)&vt16, g_vt16);

    // fp16 packs
    {
        int np;
        np = M_ * DP_;   pack16_kernel<<<np / 256, 256>>>(x,  x16,  np);
        np = D_ * DP_;   pack16_kernel<<<np / 256, 256>>>(wq, wq16, np);
        np = KVD_ * DP_; pack16_kernel<<<np / 256, 256>>>(wk, wk16, np);
        np = KVD_ * DP_; pack16_kernel<<<np / 256, 256>>>(wv, wv16, np);
        np = D_ * DP_;   pack16_kernel<<<np / 256, 256>>>(wo, wo16, np);
    }

    cudaFuncSetAttribute(gemm16<0>, cudaFuncAttributeMaxDynamicSharedMemorySize, G_SMEM);
    cudaFuncSetAttribute(gemm16<1>, cudaFuncAttributeMaxDynamicSharedMemorySize, G_SMEM);
    cudaFuncSetAttribute(gemm16<2>, cudaFuncAttributeMaxDynamicSharedMemorySize, G_SMEM);

    // projections (fp16 single-stream, 128x128 tiles, 2 CTAs/SM)
    gemm16<1><<<dim3(32, 32), 256, G_SMEM>>>(x16, wq16, nullptr, q16, fc, fs, D_, D_);
    gemm16<2><<<dim3(8,  32), 256, G_SMEM>>>(x16, wk16, nullptr, k16, fc, fs, KVD_, D_);
    gemm16<0><<<dim3(8,  32), 256, G_SMEM>>>(x16, wv16, v, nullptr, nullptr, nullptr, KVD_, D_);

    // V transpose+pack (fp16 plane)
    transpose_pack_v<<<dim3(S_ / 64, HK_, B_), 256>>>(v, vt16);

    // attention (R13 config + LPT ordering)
    cudaFuncSetAttribute(attn_mma, cudaFuncAttributeMaxDynamicSharedMemorySize, A_SMEM);
    attn_mma<<<dim3(S_ / 128, H_, B_), 256, A_SMEM>>>(q16, k16, vt16, af16);

    // output projection
    gemm16<0><<<dim3(32, 32), 256, G_SMEM>>>(af16, wo16, out, nullptr, nullptr, nullptr, D_, D_);
}

// round 16
// speedup vs baseline: 1.0696x; 1.0103x over previous
#include <cuda_runtime.h>
#include <cuda_bf16.h>
#include <cuda_fp16.h>
#include <cstdint>
#include <math.h>

#define B_   2
#define S_   2048
#define D_   4096
#define H_   32
#define HK_  8
#define HD_  128
#define M_   (B_ * S_)          // 4096 total tokens
#define KVD_ (HK_ * HD_)        // 1024
#define DP_  (D_ / 2)           // 2048 u32 pairs per row
#define SP_  (S_ / 2)           // 1024 seq pairs

// ---------------- scratch (device globals; no allocation allowed) ----------------
__device__ float    g_v[(size_t)M_ * KVD_];
// fp16 packed pair planes
__device__ unsigned g_x16[(size_t)M_ * DP_];
__device__ unsigned g_wq16[(size_t)D_ * DP_];
__device__ unsigned g_wk16[(size_t)KVD_ * DP_];
__device__ unsigned g_wv16[(size_t)KVD_ * DP_];
__device__ unsigned g_wo16[(size_t)D_ * DP_];
__device__ unsigned g_af16[(size_t)M_ * DP_];   // attention out (fp16 pairs)
__device__ unsigned g_q16[(size_t)M_ * DP_];                  // roped+scaled(log2e) Q (fp16)
__device__ unsigned g_k16[(size_t)B_ * HK_ * S_ * 64];        // roped K [b,hk,s,64]
__device__ unsigned g_vt16[(size_t)B_ * HK_ * HD_ * SP_];     // V^T [b,hk,d,s-pairs]

// ---------------- helpers ----------------
__device__ __forceinline__ unsigned packh2(float x, float y) {
    __half2 h = __floats2half2_rn(x, y);
    return *reinterpret_cast<unsigned*>(&h);
}

__device__ __forceinline__ void mma_fp16(float* c, const unsigned* a, unsigned b0, unsigned b1) {
    asm volatile(
        "mma.sync.aligned.m16n8k16.row.col.f32.f16.f16.f32 "
        "{%0,%1,%2,%3}, {%4,%5,%6,%7}, {%8,%9}, {%0,%1,%2,%3};\n"
        : "+f"(c[0]), "+f"(c[1]), "+f"(c[2]), "+f"(c[3])
        : "r"(a[0]), "r"(a[1]), "r"(a[2]), "r"(a[3]), "r"(b0), "r"(b1));
}

__device__ __forceinline__ void cpa16(unsigned saddr, const void* g) {
    asm volatile("cp.async.cg.shared.global [%0], [%1], 16;" :: "r"(saddr), "l"(g));
}

__device__ __forceinline__ uint32_t s2u(const void* p) {
    uint32_t a;
    asm("{ .reg .u64 t; cvta.to.shared.u64 t, %1; cvt.u32.u64 %0, t; }" : "=r"(a) : "l"(p));
    return a;
}

__device__ __forceinline__ void ldsm4(unsigned* r, uint32_t a) {
    asm volatile("ldmatrix.sync.aligned.m8n8.x4.shared.b16 {%0,%1,%2,%3}, [%4];"
                 : "=r"(r[0]), "=r"(r[1]), "=r"(r[2]), "=r"(r[3]) : "r"(a));
}

__device__ __forceinline__ void ldsm2(unsigned* r, uint32_t a) {
    asm volatile("ldmatrix.sync.aligned.m8n8.x2.shared.b16 {%0,%1}, [%2];"
                 : "=r"(r[0]), "=r"(r[1]) : "r"(a));
}

// ---------------- merged pack pass: all 5 fp32 -> fp16 planes, one launch ----------------
#define XBLK  (M_ * DP_ / 256)        // 32768
#define WQBLK (D_ * DP_ / 256)        // 32768
#define WKBLK (KVD_ * DP_ / 256)      // 8192
__global__ void pack_all(const float* __restrict__ x,  const float* __restrict__ wq,
                         const float* __restrict__ wk, const float* __restrict__ wv,
                         const float* __restrict__ wo,
                         unsigned* __restrict__ x16,  unsigned* __restrict__ wq16,
                         unsigned* __restrict__ wk16, unsigned* __restrict__ wv16,
                         unsigned* __restrict__ wo16)
{
    int blk = blockIdx.x;
    const float* src; unsigned* dst; int base;
    if (blk < XBLK)                        { src = x;  dst = x16;  base = blk; }
    else if (blk < XBLK + WQBLK)           { src = wq; dst = wq16; base = blk - XBLK; }
    else if (blk < XBLK + WQBLK + WKBLK)   { src = wk; dst = wk16; base = blk - XBLK - WQBLK; }
    else if (blk < XBLK + WQBLK + 2*WKBLK) { src = wv; dst = wv16; base = blk - XBLK - WQBLK - WKBLK; }
    else                                   { src = wo; dst = wo16; base = blk - XBLK - WQBLK - 2*WKBLK; }
    int i = base * 256 + threadIdx.x;
    float2 v = ((const float2*)src)[i];
    dst[i] = packh2(v.x, v.y);
}

// ---------------- transpose + pack V -> fp16 plane [b,hk,d,s-pairs] ----------------
__global__ void __launch_bounds__(256) transpose_pack_v(const float* __restrict__ V,
                                                        unsigned* __restrict__ O)
{
    __shared__ float sm[64 * 132];
    const int tid = threadIdx.x;
    const int s0  = blockIdx.x * 64;
    const int hk  = blockIdx.y;
    const int b   = blockIdx.z;

#pragma unroll
    for (int i = 0; i < 32; i++) {
        int idx = tid + i * 256;
        int r = idx >> 7, c = idx & 127;
        sm[r * 132 + c] = V[(size_t)(b * S_ + s0 + r) * KVD_ + hk * HD_ + c];
    }
    __syncthreads();

    const int d  = tid >> 1;
    const int pb = (tid & 1) * 16;
    unsigned* o = O + ((size_t)(b * HK_ + hk) * HD_ + d) * SP_ + (s0 >> 1) + pb;
#pragma unroll
    for (int i = 0; i < 16; i++) {
        int p = pb + i;
        o[i] = packh2(sm[(2 * p) * 132 + d], sm[(2 * p + 1) * 132 + d]);
    }
}

// =====================================================================
// fp16 single-stream GEMM core (ldmatrix fragments):
// C[M,N] = A[M,K]*B[N,K]^T, CTA tile 128x128, BK=64, 256 threads,
// 8 warps of 64x32, 3-stage cp.async, 2 CTAs/SM.
// mode 0: fp32 C. mode 1: rope+scale*log2e -> fp16 Q plane [row][DP_].
// mode 2: rope -> fp16 K plane [b,hk,s,64].
// =====================================================================
#define GSTR 36                       // smem row stride (u32): 32 data + 4 pad
#define APLU (128 * GSTR)             // 4608 u32
#define BPLU (128 * GSTR)             // 4608 u32
#define GSTGU (APLU + BPLU)           // 9216 u32 per stage
#define G_SMEM (3 * GSTGU * 4)        // 110592 B -> 2 CTAs/SM

__device__ __forceinline__ void gemm_core(
    const unsigned* __restrict__ Ap, const unsigned* __restrict__ Bp,
    float* __restrict__ C, unsigned* __restrict__ O16,
    const float* __restrict__ cs, const float* __restrict__ sn,
    int N, int K, int mode, int bx, int by, unsigned* gs)
{
    const int tid  = threadIdx.x;
    const int lane = tid & 31;
    const int warp = tid >> 5;
    const int m0 = by << 7;
    const int n0 = bx << 7;
    const int wm = (warp >> 2) * 64;
    const int wn = (warp & 3) * 32;
    const int grp = lane >> 2;
    const int qid = lane & 3;
    const int KP = K >> 1;

    const int lr  = tid >> 1;
    const int lc  = (tid & 1) * 16;
    const unsigned* ag = Ap + (size_t)(m0 + lr) * KP + lc;
    const unsigned* bg = Bp + (size_t)(n0 + lr) * KP + lc;

    const unsigned sbase = s2u(gs);
    const unsigned sr = (lr * GSTR + lc) * 4;

    const unsigned aoff = (unsigned)((wm + (lane & 15)) * GSTR * 4 + (lane >> 4) * 16);
    const unsigned boff = (unsigned)((wn + (lane >> 4) * 8 + (lane & 7)) * GSTR * 4
                                     + ((lane >> 3) & 1) * 16);

    float acc[4][4][4];
#pragma unroll
    for (int i = 0; i < 4; i++)
#pragma unroll
        for (int j = 0; j < 4; j++)
#pragma unroll
            for (int c = 0; c < 4; c++) acc[i][j][c] = 0.0f;

    const int nch = K / 64;

    auto issue = [&](int c, int stg) {
        unsigned sb = sbase + (unsigned)(stg * GSTGU * 4);
        const int go = c * 32;
        cpa16(sb + sr,                ag + go);
        cpa16(sb + sr + 16,           ag + go + 4);
        cpa16(sb + sr + 32,           ag + go + 8);
        cpa16(sb + sr + 48,           ag + go + 12);
        cpa16(sb + APLU * 4 + sr,      bg + go);
        cpa16(sb + APLU * 4 + sr + 16, bg + go + 4);
        cpa16(sb + APLU * 4 + sr + 32, bg + go + 8);
        cpa16(sb + APLU * 4 + sr + 48, bg + go + 12);
        asm volatile("cp.async.commit_group;");
    };

    issue(0, 0);
    if (nch > 1) issue(1, 1);

    int stg = 0;
    for (int c = 0; c < nch; c++) {
        if (c + 2 < nch) issue(c + 2, (stg + 2) % 3);
        const int rem = nch - 1 - c;
        if (rem >= 2)      { asm volatile("cp.async.wait_group 2;"); }
        else if (rem == 1) { asm volatile("cp.async.wait_group 1;"); }
        else               { asm volatile("cp.async.wait_group 0;"); }
        __syncthreads();

        const unsigned sA = sbase + (unsigned)(stg * GSTGU * 4);
        const unsigned sB = sA + APLU * 4;

#pragma unroll
        for (int kk = 0; kk < 4; kk++) {
            unsigned af[4][4];
#pragma unroll
            for (int mi = 0; mi < 4; mi++)
                ldsm4(af[mi], sA + aoff + mi * (16 * GSTR * 4) + kk * 32);
#pragma unroll
            for (int njp = 0; njp < 2; njp++) {
                unsigned bf[4];
                ldsm4(bf, sB + boff + njp * (16 * GSTR * 4) + kk * 32);
#pragma unroll
                for (int mi = 0; mi < 4; mi++) {
                    mma_fp16(acc[mi][2 * njp],     af[mi], bf[0], bf[1]);
                    mma_fp16(acc[mi][2 * njp + 1], af[mi], bf[2], bf[3]);
                }
            }
        }
        __syncthreads();
        stg = (stg + 1) % 3;
    }

    // ---- epilogue ----
#pragma unroll
    for (int mi = 0; mi < 4; mi++) {
        int row0 = m0 + wm + mi * 16 + grp;
#pragma unroll
        for (int nj = 0; nj < 4; nj++) {
            int col = n0 + wn + nj * 8 + qid * 2;
            if (mode == 0) {
                *(float2*)(C + (size_t)row0 * N + col) =
                    make_float2(acc[mi][nj][0], acc[mi][nj][1]);
                *(float2*)(C + (size_t)(row0 + 8) * N + col) =
                    make_float2(acc[mi][nj][2], acc[mi][nj][3]);
            } else {
                const int d2 = (col >> 1) & 63;
#pragma unroll
                for (int half = 0; half < 2; half++) {
                    int r = row0 + half * 8;
                    float x0 = acc[mi][nj][half * 2];
                    float x1 = acc[mi][nj][half * 2 + 1];
                    int s = r & (S_ - 1);
                    float cc = cs[s * 64 + d2];
                    float sv = sn[s * 64 + d2];
                    float o0 = x0 * cc - x1 * sv;
                    float o1 = x0 * sv + x1 * cc;
                    if (mode == 1) {
                        // 1/sqrt(128) * log2(e): logits emerge in log2 domain
                        const float scale = 0.08838834764831845f * 1.4426950408889634f;
                        o0 *= scale; o1 *= scale;
                    }
                    size_t o;
                    if (mode == 1) o = (size_t)r * DP_ + (col >> 1);
                    else {
                        int b = r >> 11, ss = r & (S_ - 1), hk = col >> 7;
                        o = ((size_t)(b * HK_ + hk) * S_ + ss) * 64 + d2;
                    }
                    O16[o] = packh2(o0, o1);
                }
            }
        }
    }
}

// ---- merged QKV projection: 1536 CTAs, one launch ----
__global__ void __launch_bounds__(256, 2)
qkv_kernel(const unsigned* __restrict__ x16,
           const unsigned* __restrict__ wq16, const unsigned* __restrict__ wk16,
           const unsigned* __restrict__ wv16,
           unsigned* __restrict__ q16, unsigned* __restrict__ k16,
           float* __restrict__ v,
           const float* __restrict__ cs, const float* __restrict__ sn)
{
    extern __shared__ unsigned gs[];
    const int idx = blockIdx.x;
    const unsigned* Bp;
    unsigned* O16 = nullptr;
    float* C = nullptr;
    int mode, bx, by, N;
    if (idx < 1024)       { Bp = wq16; O16 = q16; mode = 1; N = D_;   bx = idx & 31;  by = idx >> 5; }
    else if (idx < 1280)  { int l = idx - 1024; Bp = wk16; O16 = k16; mode = 2; N = KVD_; bx = l & 7; by = l >> 3; }
    else                  { int l = idx - 1280; Bp = wv16; C = v;     mode = 0; N = KVD_; bx = l & 7; by = l >> 3; }
    gemm_core(x16, Bp, C, O16, cs, sn, N, D_, mode, bx, by, gs);
}

// ---- WO projection ----
__global__ void __launch_bounds__(256, 2)
wo_kernel(const unsigned* __restrict__ af16, const unsigned* __restrict__ wo16,
          float* __restrict__ out)
{
    extern __shared__ unsigned gs[];
    gemm_core(af16, wo16, out, nullptr, nullptr, nullptr, D_, D_, 0,
              blockIdx.x, blockIdx.y, gs);
}

// =====================================================================
// Flash attention (R13 config): fp16 MMA, log2-domain h2exp2 softmax,
// ones-column denominator. BM=128, BN=64, 3-stage, 1 CTA/SM. LPT order.
// =====================================================================
#define KSTR 68                          // K row stride (u32): 64 + 4
#define VSTR 36                          // Vt/P row stride (u32): 32 + 4
#define VROWS 136                        // 128 d-rows + ones row + 7 zero rows
#define KPLU (64 * KSTR)                 // 4352 u32
#define VPLU (VROWS * VSTR)              // 4896 u32
#define ASTGU (KPLU + VPLU)              // 9248 u32 per stage
#define PPLU (128 * VSTR)                // 4608 u32 (P tile)
#define A_SMEM ((3 * ASTGU + PPLU) * 4)  // 129408 B -> 1 CTA/SM

__global__ void __launch_bounds__(256, 1) attn_mma(const unsigned* __restrict__ Q16,
                                                   const unsigned* __restrict__ K16,
                                                   const unsigned* __restrict__ Vt16,
                                                   unsigned* __restrict__ Of16)
{
    extern __shared__ unsigned smu[];
    const unsigned sm_base = s2u(smu);
    unsigned* Ps = smu + 3 * ASTGU;
    const unsigned pbb = sm_base + (unsigned)(3 * ASTGU * 4);

    const int tid  = threadIdx.x;
    const int lane = tid & 31;
    const int warp = tid >> 5;
    const int grp  = lane >> 2;
    const int qid  = lane & 3;
    const int qt = (S_ / 128 - 1) - blockIdx.x;   // LPT: longest first
    const int h  = blockIdx.y;
    const int b  = blockIdx.z;
    const int hk = h >> 2;
    const int q0  = qt * 128;
    const int wq0 = warp * 16;

    const unsigned* kb = K16  + (size_t)(b * HK_ + hk) * S_ * 64;
    const unsigned* vb = Vt16 + (size_t)(b * HK_ + hk) * HD_ * SP_;

    const unsigned koff = (unsigned)(((lane >> 4) * 8 + (lane & 7)) * KSTR * 4
                                     + ((lane >> 3) & 1) * 16);
    const unsigned voff = (unsigned)(((lane >> 4) * 8 + (lane & 7)) * VSTR * 4
                                     + ((lane >> 3) & 1) * 16);
    const unsigned poff = (unsigned)((wq0 + (lane & 15)) * VSTR * 4 + (lane >> 4) * 16);
    const int la = lane & 15;
    const unsigned loff = (unsigned)((128 + (la & 7)) * VSTR * 4 + (la >> 3) * 16);

    // init constant ones/zero rows 128..135 in all 3 stages
    for (int i = tid; i < 3 * 8 * 32; i += 256) {
        int stg = i / 256;
        int rr  = (i >> 5) & 7;
        int cc  = i & 31;
        smu[stg * ASTGU + KPLU + (128 + rr) * VSTR + cc] = (rr == 0) ? 0x3C003C00u : 0u;
    }

    unsigned qf[8][4];
    {
        const unsigned* qp = Q16 + (size_t)(b * S_ + q0 + wq0) * DP_ + h * 64;
#pragma unroll
        for (int kk = 0; kk < 8; kk++) {
            qf[kk][0] = qp[(size_t)grp * DP_ + kk * 8 + qid];
            qf[kk][1] = qp[(size_t)(grp + 8) * DP_ + kk * 8 + qid];
            qf[kk][2] = qp[(size_t)grp * DP_ + kk * 8 + qid + 4];
            qf[kk][3] = qp[(size_t)(grp + 8) * DP_ + kk * 8 + qid + 4];
        }
    }

    float o_acc[16][4];
#pragma unroll
    for (int i = 0; i < 16; i++)
#pragma unroll
        for (int c = 0; c < 4; c++) o_acc[i][c] = 0.0f;
    float o_l[4] = {0.0f, 0.0f, 0.0f, 0.0f};
    float m0r = -1e30f, m1r = -1e30f;

    const int qrow0 = q0 + wq0 + grp;
    const int tmax = 2 * qt + 1;

    const int krr = tid >> 2;
    const int kcc = tid & 3;
    const int vrr = tid >> 1;
    const int vcc = tid & 1;

    auto issueT = [&](int tt, int stg) {
        const unsigned sb = sm_base + (unsigned)(stg * ASTGU * 4);
        const int kv = tt * 64;
        const unsigned* gk = kb + (size_t)(kv + krr) * 64 + kcc * 4;
        const unsigned ks = sb + krr * (KSTR * 4) + kcc * 16;
#pragma unroll
        for (int j = 0; j < 4; j++) cpa16(ks + j * 64, gk + j * 16);
        const unsigned* gv = vb + (size_t)vrr * SP_ + (kv >> 1) + vcc * 4;
        const unsigned vs = sb + KPLU * 4 + vrr * (VSTR * 4) + vcc * 16;
#pragma unroll
        for (int j = 0; j < 4; j++) cpa16(vs + j * 32, gv + j * 8);
        asm volatile("cp.async.commit_group;");
    };

    issueT(0, 0);
    if (tmax >= 1) issueT(1, 1);

    int stg = 0;
    for (int t = 0; t <= tmax; t++) {
        const int kv0 = t * 64;
        if (t + 2 <= tmax) issueT(t + 2, (stg + 2) % 3);
        const int rem = tmax - t;
        if (rem >= 2)      { asm volatile("cp.async.wait_group 2;"); }
        else if (rem == 1) { asm volatile("cp.async.wait_group 1;"); }
        else               { asm volatile("cp.async.wait_group 0;"); }
        __syncthreads();

        if (kv0 <= q0 + wq0 + 15) {
            const unsigned skh = sm_base + (unsigned)(stg * ASTGU * 4);
            const unsigned svh = skh + (unsigned)(KPLU * 4);

            float s[8][4];
#pragma unroll
            for (int nj = 0; nj < 8; nj++)
#pragma unroll
                for (int c = 0; c < 4; c++) s[nj][c] = 0.0f;

#pragma unroll
            for (int kk = 0; kk < 8; kk++) {
#pragma unroll
                for (int njp = 0; njp < 4; njp++) {
                    unsigned bf[4];
                    ldsm4(bf, skh + koff + njp * (16 * KSTR * 4) + kk * 32);
                    mma_fp16(s[2 * njp],     qf[kk], bf[0], bf[1]);
                    mma_fp16(s[2 * njp + 1], qf[kk], bf[2], bf[3]);
                }
            }

            if (kv0 + 63 > q0 + wq0) {
#pragma unroll
                for (int nj = 0; nj < 8; nj++) {
                    int kcol = kv0 + nj * 8 + 2 * qid;
                    if (kcol     > qrow0)     s[nj][0] = -1e30f;
                    if (kcol + 1 > qrow0)     s[nj][1] = -1e30f;
                    if (kcol     > qrow0 + 8) s[nj][2] = -1e30f;
                    if (kcol + 1 > qrow0 + 8) s[nj][3] = -1e30f;
                }
            }

            float rm0 = -1e30f, rm1 = -1e30f;
#pragma unroll
            for (int nj = 0; nj < 8; nj++) {
                rm0 = fmaxf(rm0, fmaxf(s[nj][0], s[nj][1]));
                rm1 = fmaxf(rm1, fmaxf(s[nj][2], s[nj][3]));
            }
            rm0 = fmaxf(rm0, __shfl_xor_sync(0xffffffffu, rm0, 1));
            rm0 = fmaxf(rm0, __shfl_xor_sync(0xffffffffu, rm0, 2));
            rm1 = fmaxf(rm1, __shfl_xor_sync(0xffffffffu, rm1, 1));
            rm1 = fmaxf(rm1, __shfl_xor_sync(0xffffffffu, rm1, 2));

            float mn0 = fmaxf(m0r, rm0), mn1 = fmaxf(m1r, rm1);
            float a0 = exp2f(m0r - mn0), a1 = exp2f(m1r - mn1);
            m0r = mn0; m1r = mn1;

#pragma unroll
            for (int nj = 0; nj < 8; nj++) {
                __half2 p0 = h2exp2(__floats2half2_rn(s[nj][0] - mn0, s[nj][1] - mn0));
                Ps[(wq0 + grp) * VSTR + nj * 4 + qid] = *reinterpret_cast<unsigned*>(&p0);
                __half2 p1 = h2exp2(__floats2half2_rn(s[nj][2] - mn1, s[nj][3] - mn1));
                Ps[(wq0 + grp + 8) * VSTR + nj * 4 + qid] = *reinterpret_cast<unsigned*>(&p1);
            }

#pragma unroll
            for (int nj = 0; nj < 16; nj++) {
                o_acc[nj][0] *= a0; o_acc[nj][1] *= a0;
                o_acc[nj][2] *= a1; o_acc[nj][3] *= a1;
            }
            o_l[0] *= a0; o_l[1] *= a0; o_l[2] *= a1; o_l[3] *= a1;
            __syncwarp();

#pragma unroll
            for (int kk = 0; kk < 4; kk++) {
                unsigned pa[4];
                ldsm4(pa, pbb + poff + kk * 32);
#pragma unroll
                for (int njp = 0; njp < 8; njp++) {
                    unsigned vf[4];
                    ldsm4(vf, svh + voff + njp * (16 * VSTR * 4) + kk * 32);
                    mma_fp16(o_acc[2 * njp],     pa, vf[0], vf[1]);
                    mma_fp16(o_acc[2 * njp + 1], pa, vf[2], vf[3]);
                }
                unsigned lf[2];
                ldsm2(lf, svh + loff + kk * 32);
                mma_fp16(o_l, pa, lf[0], lf[1]);
            }
        }
        __syncthreads();
        stg = (stg + 1) % 3;
    }

    const int src = lane & ~3;
    const float l0 = __shfl_sync(0xffffffffu, o_l[0], src);
    const float l1 = __shfl_sync(0xffffffffu, o_l[2], src);
    const float il0 = 1.0f / l0;
    const float il1 = 1.0f / l1;
    const size_t r0 = (size_t)(b * S_ + q0 + wq0 + grp) * DP_;
    const size_t r1 = (size_t)(b * S_ + q0 + wq0 + grp + 8) * DP_;
#pragma unroll
    for (int nj = 0; nj < 16; nj++) {
        int col = h * 64 + nj * 4 + qid;
        Of16[r0 + col] = packh2(o_acc[nj][0] * il0, o_acc[nj][1] * il0);
        Of16[r1 + col] = packh2(o_acc[nj][2] * il1, o_acc[nj][3] * il1);
    }
}

// =====================================================================
// launch
// =====================================================================
extern "C" void kernel_launch(void* const* d_in, const int* in_sizes, int n_in,
                              void* d_out, int out_size)
{
    const float* x  = (const float*)d_in[0];
    const float* fc = (const float*)d_in[1];
    const float* fs = (const float*)d_in[2];
    const float* wq = (const float*)d_in[3];
    const float* wk = (const float*)d_in[4];
    const float* wv = (const float*)d_in[5];
    const float* wo = (const float*)d_in[6];
    float* out = (float*)d_out;

    float *v;
    unsigned *x16, *wq16, *wk16, *wv16, *wo16, *af16, *q16, *k16, *vt16;
    cudaGetSymbolAddress((void**)&v,    g_v);
    cudaGetSymbolAddress((void**)&x16,  g_x16);
    cudaGetSymbolAddress((void**)&wq16, g_wq16);
    cudaGetSymbolAddress((void**)&wk16, g_wk16);
    cudaGetSymbolAddress((void**)&wv16, g_wv16);
    cudaGetSymbolAddress((void**)&wo16, g_wo16);
    cudaGetSymbolAddress((void**)&af16, g_af16);
    cudaGetSymbolAddress((void**)&q16,  g_q16);
    cudaGetSymbolAddress((void**)&k16,  g_k16);
    cudaGetSymbolAddress((void**)&vt16, g_vt16);

    // merged fp16 packs (one launch)
    {
        const int total = XBLK + WQBLK + 3 * WKBLK + WQBLK;  // x,wq,wk,wv,wo... compute directly
        const int nblk = XBLK + WQBLK + 2 * WKBLK + (D_ * DP_ / 256);
        (void)total;
        pack_all<<<nblk, 256>>>(x, wq, wk, wv, wo, x16, wq16, wk16, wv16, wo16);
    }

    cudaFuncSetAttribute(qkv_kernel, cudaFuncAttributeMaxDynamicSharedMemorySize, G_SMEM);
    cudaFuncSetAttribute(wo_kernel,  cudaFuncAttributeMaxDynamicSharedMemorySize, G_SMEM);

    // merged QKV projections (one launch: 1024 Q + 256 K + 256 V CTAs)
    qkv_kernel<<<1536, 256, G_SMEM>>>(x16, wq16, wk16, wv16, q16, k16, v, fc, fs);

    // V transpose+pack (fp16 plane)
    transpose_pack_v<<<dim3(S_ / 64, HK_, B_), 256>>>(v, vt16);

    // attention (R13 config + LPT ordering)
    cudaFuncSetAttribute(attn_mma, cudaFuncAttributeMaxDynamicSharedMemorySize, A_SMEM);
    attn_mma<<<dim3(S_ / 128, H_, B_), 256, A_SMEM>>>(q16, k16, vt16, af16);

    // output projection
    wo_kernel<<<dim3(32, 32), 256, G_SMEM>>>(af16, wo16, out);
}